// round 15
// baseline (speedup 1.0000x reference)
#include <cuda_runtime.h>
#include <cuda_bf16.h>
#include <cstdint>

// ===========================================================================
// TrainableTree: out[n] = a(x_n) * ( sin(Wt x_n + bt) . w_eff + c )
// Tree after sin() is linear with OUT=1 -> collapses to (w_eff[64], c).
// compose_kernel: 16 blocks, double-buffered weight prefetch; PDL trigger.
// tree_main_kernel (PDL secondary): prologue overlaps compose; hot loop has a
//   ROLLED nt-loop (~16-instr body) to fit the L0 I-cache — the working
//   theory is that the unrolled ~6KB body was fetch-thrashing L0.
// Main loop: HMMA (bf16 hi/lo split, fp32 accum) -> MUFU sin -> dot.
// ===========================================================================

__device__ float g_part[16][64];   // per-leaf partials of w_eff
__device__ float c_part[16];       // per-leaf partials of c

// ---------------- helpers ----------------
__device__ __forceinline__ uint32_t bfpk(float lo, float hi) {
    uint32_t d;
    asm("cvt.rn.bf16x2.f32 %0, %1, %2;" : "=r"(d) : "f"(hi), "f"(lo));
    return d;   // lower 16 = bf16(lo), upper 16 = bf16(hi)
}
__device__ __forceinline__ float bflo(uint32_t p) { return __uint_as_float(p << 16); }
__device__ __forceinline__ float bfhi(uint32_t p) { return __uint_as_float(p & 0xffff0000u); }

// ---------------------------------------------------------------------------
// Compose: 16 blocks x 256 thr, double-buffered weight prefetch (no spills).
// ---------------------------------------------------------------------------
__global__ void __launch_bounds__(256)
compose_kernel(const float* __restrict__ Wleaf, const float* __restrict__ bleaf,
               const float* __restrict__ W3, const float* __restrict__ b3,
               const float* __restrict__ W2, const float* __restrict__ b2,
               const float* __restrict__ W1, const float* __restrict__ b1,
               const float* __restrict__ Wr, const float* __restrict__ br) {
    __shared__ float sGr[64], sG1[64], sG2[64], sG3[64];
    __shared__ float red[4][64];
    __shared__ float cp[64];

    const int t = threadIdx.x;
    const int k = blockIdx.x;
    const int o = t & 63, q = t >> 6;   // q in 0..3
    const int p0 = q * 16;

    const float* W1n = W1 + (k >> 3) * 4096;
    const float* W2n = W2 + (k >> 2) * 4096;
    const float* W3n = W3 + (k >> 1) * 4096;
    const float* WLn = Wleaf + k * 4096;

    float wA[16], wB[16];
    #pragma unroll
    for (int i = 0; i < 16; i++) wA[i] = W1n[(p0 + i) * 64 + o];   // stage 1
    if (t < 64) sGr[t] = Wr[t];
    __syncthreads();

    #pragma unroll
    for (int i = 0; i < 16; i++) wB[i] = W2n[(p0 + i) * 64 + o];
    {
        float s = 0.f;
        #pragma unroll
        for (int i = 0; i < 16; i++) s = fmaf(wA[i], sGr[p0 + i], s);
        red[q][o] = s;
    }
    __syncthreads();
    if (t < 64) sG1[t] = red[0][t] + red[1][t] + red[2][t] + red[3][t];
    __syncthreads();

    #pragma unroll
    for (int i = 0; i < 16; i++) wA[i] = W3n[(p0 + i) * 64 + o];
    {
        float s = 0.f;
        #pragma unroll
        for (int i = 0; i < 16; i++) s = fmaf(wB[i], sG1[p0 + i], s);
        red[q][o] = s;
    }
    __syncthreads();
    if (t < 64) sG2[t] = red[0][t] + red[1][t] + red[2][t] + red[3][t];
    __syncthreads();

    #pragma unroll
    for (int i = 0; i < 16; i++) wB[i] = WLn[(p0 + i) * 64 + o];
    {
        float s = 0.f;
        #pragma unroll
        for (int i = 0; i < 16; i++) s = fmaf(wA[i], sG2[p0 + i], s);
        red[q][o] = s;
    }
    __syncthreads();
    if (t < 64) sG3[t] = red[0][t] + red[1][t] + red[2][t] + red[3][t];
    __syncthreads();

    {
        float s = 0.f;
        #pragma unroll
        for (int i = 0; i < 16; i++) s = fmaf(wB[i], sG3[p0 + i], s);
        red[q][o] = s;
    }
    __syncthreads();
    if (t < 64) g_part[k][t] = red[0][t] + red[1][t] + red[2][t] + red[3][t];

    if (t < 64) {
        float s = sG3[o] * bleaf[k * 64 + o];
        if ((k & 1) == 0) s = fmaf(sG2[o], b3[(k >> 1) * 64 + o], s);
        if ((k & 3) == 0) s = fmaf(sG1[o], b2[(k >> 2) * 64 + o], s);
        if (k == 0)       s = fmaf(sGr[o], b1[o] + b1[64 + o], s);
        cp[o] = s;
    }
    __syncthreads();
    if (t == 0) {
        float s = (k == 0) ? br[0] : 0.f;
        #pragma unroll 8
        for (int i = 0; i < 64; i++) s += cp[i];
        c_part[k] = s;
    }
    __syncthreads();

    // All results written: allow dependent (main) kernel to proceed.
    cudaTriggerProgrammaticLaunchCompletion();
}

// ---------------------------------------------------------------------------
// Main kernel (PDL secondary). 16 samples per warp-iteration.
//   A (x) tile: 16 rows x 32 K bf16 in smem (80B rows, conflict-free ldmatrix)
//   Row words: [H0..H4 L0 L1 L2 | L3 L4 H0..H4 ONES]   (H=x_hi, L=x_lo pairs)
//   B cols:    [W_hi(10) | W_hi(10) | W_lo(10) | bt_hi, bt_lo]
//   h = x_hi.W_hi + x_lo.W_hi + x_hi.W_lo + bt   (fp32 accum, ~1e-5 rel)
//   The nt loop is ROLLED (unroll 1) to keep the loop body inside L0 I$.
// ---------------------------------------------------------------------------
__global__ void __launch_bounds__(128, 8)
tree_main_kernel(const float* __restrict__ x, const float* __restrict__ Wt,
                 const float* __restrict__ bt, float* __restrict__ out,
                 int N, int n_chunks) {
    __shared__ uint32_t sB[64][18];       // [out][k-pair], 72B rows
    __shared__ uint32_t sA[4][16][20];    // per warp: 16 rows x 80B
    __shared__ uint4 sFrag[8][32];        // [n-tile][lane]
    __shared__ float sWeff[64];
    __shared__ float sC[1];

    const int t = threadIdx.x;
    const int wid = t >> 5, lane = t & 31;
    const int c = lane & 3, g = lane >> 2;

    // ---- build B tile (independent of compose; overlaps it under PDL) ----
    if (t < 64) {
        const float2* wr = (const float2*)(Wt + t * 10);
        uint32_t H[5], L[5];
        #pragma unroll
        for (int j = 0; j < 5; j++) {
            const float2 v = wr[j];
            H[j] = bfpk(v.x, v.y);
            L[j] = bfpk(v.x - bflo(H[j]), v.y - bfhi(H[j]));
        }
        const float bv = bt[t];
        const uint32_t bh = bfpk(bv, 0.f);
        const uint32_t bp = bfpk(bv, bv - bflo(bh));   // {bt_hi, bt_lo}
        #pragma unroll
        for (int j = 0; j < 5; j++) {
            sB[t][j]      = H[j];   // k 0-9  : W_hi
            sB[t][5 + j]  = H[j];   // k 10-19: W_hi
            sB[t][10 + j] = L[j];   // k 20-29: W_lo
        }
        sB[t][15] = bp;             // k 30,31: bt_hi, bt_lo
        sB[t][16] = 0u; sB[t][17] = 0u;
    }
    __syncthreads();

    // ---- precompute per-lane B fragments into smem (warp 0) ----
    if (wid == 0) {
        #pragma unroll
        for (int nt = 0; nt < 8; nt++) {
            const int row = 8 * nt + g;
            sFrag[nt][lane] = make_uint4(sB[row][c],     sB[row][4 + c],
                                         sB[row][8 + c], sB[row][12 + c]);
        }
    }

    // ---- wait for compose results, then reduce w_eff / c ----
    cudaGridDependencySynchronize();
    if (t < 64) {
        float s = 0.f;
        #pragma unroll
        for (int k = 0; k < 16; k++) s += g_part[k][t];
        sWeff[t] = s;
    }
    if (t == 64) {
        float s = 0.f;
        #pragma unroll
        for (int k = 0; k < 16; k++) s += c_part[k];
        sC[0] = s;
    }
    __syncthreads();
    const float cv = sC[0];

    const int s16 = lane & 15;
    const bool hi_half = (lane >= 16);
    const int lm_sub = lane >> 3, lm_r = lane & 7;
    const int lm_row = lm_r + 8 * (lm_sub & 1);
    const uint32_t lm_base =
        (uint32_t)__cvta_generic_to_shared(&sA[wid][lm_row][0]) + (lm_sub >> 1) * 16;

    const uint32_t frag_base =
        (uint32_t)__cvta_generic_to_shared(&sFrag[0][lane]);
    const uint32_t weff_base =
        (uint32_t)__cvta_generic_to_shared(&sWeff[2 * c]);

    const int wglobal = blockIdx.x * 4 + wid;
    const int wstride = gridDim.x * 4;

    for (int ch = wglobal; ch < n_chunks; ch += wstride) {
        const int row = ch * 16 + s16;
        float xv[10];
        {
            const float2* p = (const float2*)(x + (size_t)row * 10);
            #pragma unroll
            for (int i = 0; i < 5; i++) { float2 v = p[i]; xv[2*i] = v.x; xv[2*i+1] = v.y; }
        }

        // envelope
        float env = fmaf(xv[0], xv[0], -1.f);
        #pragma unroll
        for (int d = 1; d < 10; d++) env *= fmaf(xv[d], xv[d], -1.f);
        env = env * rsqrtf(fmaf(env, env, 1000.f));

        // ---- branchless A staging ----
        uint32_t H[5], L[5];
        #pragma unroll
        for (int j = 0; j < 5; j++) {
            H[j] = bfpk(xv[2 * j], xv[2 * j + 1]);
            L[j] = bfpk(xv[2 * j] - bflo(H[j]), xv[2 * j + 1] - bfhi(H[j]));
        }
        const uint32_t w0 = hi_half ? L[3] : H[0];
        const uint32_t w1 = hi_half ? L[4] : H[1];
        const uint32_t w2 = hi_half ? H[0] : H[2];
        const uint32_t w3 = hi_half ? H[1] : H[3];
        const uint32_t w4 = hi_half ? H[2] : H[4];
        const uint32_t w5 = hi_half ? H[3] : L[0];
        const uint32_t w6 = hi_half ? H[4] : L[1];
        const uint32_t w7 = hi_half ? 0x3f803f80u : L[2];
        uint32_t* dst = &sA[wid][s16][(lane >> 4) << 3];
        *(uint4*)dst       = make_uint4(w0, w1, w2, w3);
        *(uint4*)(dst + 4) = make_uint4(w4, w5, w6, w7);
        __syncwarp();

        uint32_t a0[4], a1[4];
        asm volatile("ldmatrix.sync.aligned.m8n8.x4.shared.b16 {%0,%1,%2,%3}, [%4];"
                     : "=r"(a0[0]), "=r"(a0[1]), "=r"(a0[2]), "=r"(a0[3])
                     : "r"(lm_base));
        asm volatile("ldmatrix.sync.aligned.m8n8.x4.shared.b16 {%0,%1,%2,%3}, [%4];"
                     : "=r"(a1[0]), "=r"(a1[1]), "=r"(a1[2]), "=r"(a1[3])
                     : "r"(lm_base + 32));

        // ---- ROLLED nt loop: tiny body, fits L0 I$ ----
        float accA = 0.f, accB = 0.f;
        uint32_t fp = frag_base;
        uint32_t wp = weff_base;
        #pragma unroll 1
        for (int nt = 0; nt < 8; nt++) {
            uint4 bf;
            asm volatile("ld.shared.v4.u32 {%0,%1,%2,%3}, [%4];"
                         : "=r"(bf.x), "=r"(bf.y), "=r"(bf.z), "=r"(bf.w)
                         : "r"(fp));
            float2 wv;
            asm volatile("ld.shared.v2.f32 {%0,%1}, [%2];"
                         : "=f"(wv.x), "=f"(wv.y) : "r"(wp));
            float d0 = 0.f, d1 = 0.f, d2 = 0.f, d3 = 0.f;
            asm volatile(
                "mma.sync.aligned.m16n8k16.row.col.f32.bf16.bf16.f32 "
                "{%0,%1,%2,%3}, {%4,%5,%6,%7}, {%8,%9}, {%0,%1,%2,%3};"
                : "+f"(d0), "+f"(d1), "+f"(d2), "+f"(d3)
                : "r"(a0[0]), "r"(a0[1]), "r"(a0[2]), "r"(a0[3]),
                  "r"(bf.x), "r"(bf.y));
            asm volatile(
                "mma.sync.aligned.m16n8k16.row.col.f32.bf16.bf16.f32 "
                "{%0,%1,%2,%3}, {%4,%5,%6,%7}, {%8,%9}, {%0,%1,%2,%3};"
                : "+f"(d0), "+f"(d1), "+f"(d2), "+f"(d3)
                : "r"(a1[0]), "r"(a1[1]), "r"(a1[2]), "r"(a1[3]),
                  "r"(bf.z), "r"(bf.w));

            float s0, s1v, s2v, s3v;
            asm("sin.approx.f32 %0, %1;" : "=f"(s0)  : "f"(d0));
            asm("sin.approx.f32 %0, %1;" : "=f"(s1v) : "f"(d1));
            asm("sin.approx.f32 %0, %1;" : "=f"(s2v) : "f"(d2));
            asm("sin.approx.f32 %0, %1;" : "=f"(s3v) : "f"(d3));
            accA = fmaf(s0,  wv.x, accA);
            accA = fmaf(s1v, wv.y, accA);
            accB = fmaf(s2v, wv.x, accB);
            accB = fmaf(s3v, wv.y, accB);

            fp += 32 * 16;   // next sFrag row (32 uint4)
            wp += 8 * 4;     // next 8 floats of sWeff
        }

        // reduce over the 4 lanes (c=0..3) sharing the same sample rows
        accA += __shfl_xor_sync(0xffffffffu, accA, 1);
        accA += __shfl_xor_sync(0xffffffffu, accA, 2);
        accB += __shfl_xor_sync(0xffffffffu, accB, 1);
        accB += __shfl_xor_sync(0xffffffffu, accB, 2);

        const float envG  = __shfl_sync(0xffffffffu, env, g);
        const float envG8 = __shfl_sync(0xffffffffu, env, g + 8);

        const int base = ch * 16;
        if (c == 0 && base + g < N)     out[base + g]     = envG  * (accA + cv);
        if (c == 1 && base + g + 8 < N) out[base + g + 8] = envG8 * (accB + cv);
    }
}

// ---------------------------------------------------------------------------
extern "C" void kernel_launch(void* const* d_in, const int* in_sizes, int n_in,
                              void* d_out, int out_size) {
    const float* x     = (const float*)d_in[0];
    const float* Wt    = (const float*)d_in[1];
    const float* bt    = (const float*)d_in[2];
    const float* Wleaf = (const float*)d_in[3];
    const float* bleaf = (const float*)d_in[4];
    const float* W3    = (const float*)d_in[5];
    const float* b3    = (const float*)d_in[6];
    const float* W2    = (const float*)d_in[7];
    const float* b2    = (const float*)d_in[8];
    const float* W1    = (const float*)d_in[9];
    const float* b1    = (const float*)d_in[10];
    const float* Wr    = (const float*)d_in[11];
    const float* br    = (const float*)d_in[12];
    float* out = (float*)d_out;

    const int N = in_sizes[0] / 10;
    const int n_chunks = (N + 15) / 16;

    compose_kernel<<<16, 256>>>(Wleaf, bleaf, W3, b3, W2, b2, W1, b1, Wr, br);

    // Main kernel as PDL secondary: prologue overlaps compose.
    int grid = (n_chunks + 15) / 16;      // 1024 for N=262144
    if (grid < 1) grid = 1;

    cudaLaunchConfig_t cfg = {};
    cfg.gridDim = dim3((unsigned)grid, 1, 1);
    cfg.blockDim = dim3(128, 1, 1);
    cfg.dynamicSmemBytes = 0;
    cudaLaunchAttribute attrs[1];
    attrs[0].id = cudaLaunchAttributeProgrammaticStreamSerialization;
    attrs[0].val.programmaticStreamSerializationAllowed = 1;
    cfg.attrs = attrs;
    cfg.numAttrs = 1;
    cudaLaunchKernelEx(&cfg, tree_main_kernel, x, Wt, bt, out, N, n_chunks);
}

// round 16
// speedup vs baseline: 1.1120x; 1.1120x over previous
#include <cuda_runtime.h>
#include <cuda_bf16.h>
#include <cstdint>

// ===========================================================================
// TrainableTree: out[n] = a(x_n) * ( sin(Wt x_n + bt) . w_eff + c )
// Tree after sin() is linear with OUT=1 -> collapses to (w_eff[64], c).
// compose_kernel: 16 blocks, double-buffered weight prefetch; PDL trigger.
// tree_main_kernel (PDL secondary): 2 chunks (32 samples) per warp-iteration
//   with PER-LANE staging (each lane owns ONE distinct sample: loads, splits,
//   envelopes, and writes its full A row) — removes the duplicated staging
//   that made R10 neutral. HMMA (bf16 hi/lo split) -> MUFU sin -> dot.
// ===========================================================================

__device__ float g_part[16][64];   // per-leaf partials of w_eff
__device__ float c_part[16];       // per-leaf partials of c

// ---------------- helpers ----------------
__device__ __forceinline__ uint32_t bfpk(float lo, float hi) {
    uint32_t d;
    asm("cvt.rn.bf16x2.f32 %0, %1, %2;" : "=r"(d) : "f"(hi), "f"(lo));
    return d;   // lower 16 = bf16(lo), upper 16 = bf16(hi)
}
__device__ __forceinline__ float bflo(uint32_t p) { return __uint_as_float(p << 16); }
__device__ __forceinline__ float bfhi(uint32_t p) { return __uint_as_float(p & 0xffff0000u); }

#define MMA16816(d0,d1,d2,d3,a,b0,b1) \
    asm volatile( \
        "mma.sync.aligned.m16n8k16.row.col.f32.bf16.bf16.f32 " \
        "{%0,%1,%2,%3}, {%4,%5,%6,%7}, {%8,%9}, {%0,%1,%2,%3};" \
        : "+f"(d0), "+f"(d1), "+f"(d2), "+f"(d3) \
        : "r"((a)[0]), "r"((a)[1]), "r"((a)[2]), "r"((a)[3]), \
          "r"(b0), "r"(b1))

// ---------------------------------------------------------------------------
// Compose: 16 blocks x 256 thr, double-buffered weight prefetch (no spills).
// ---------------------------------------------------------------------------
__global__ void __launch_bounds__(256)
compose_kernel(const float* __restrict__ Wleaf, const float* __restrict__ bleaf,
               const float* __restrict__ W3, const float* __restrict__ b3,
               const float* __restrict__ W2, const float* __restrict__ b2,
               const float* __restrict__ W1, const float* __restrict__ b1,
               const float* __restrict__ Wr, const float* __restrict__ br) {
    __shared__ float sGr[64], sG1[64], sG2[64], sG3[64];
    __shared__ float red[4][64];
    __shared__ float cp[64];

    const int t = threadIdx.x;
    const int k = blockIdx.x;
    const int o = t & 63, q = t >> 6;   // q in 0..3
    const int p0 = q * 16;

    const float* W1n = W1 + (k >> 3) * 4096;
    const float* W2n = W2 + (k >> 2) * 4096;
    const float* W3n = W3 + (k >> 1) * 4096;
    const float* WLn = Wleaf + k * 4096;

    float wA[16], wB[16];
    #pragma unroll
    for (int i = 0; i < 16; i++) wA[i] = W1n[(p0 + i) * 64 + o];   // stage 1
    if (t < 64) sGr[t] = Wr[t];
    __syncthreads();

    #pragma unroll
    for (int i = 0; i < 16; i++) wB[i] = W2n[(p0 + i) * 64 + o];
    {
        float s = 0.f;
        #pragma unroll
        for (int i = 0; i < 16; i++) s = fmaf(wA[i], sGr[p0 + i], s);
        red[q][o] = s;
    }
    __syncthreads();
    if (t < 64) sG1[t] = red[0][t] + red[1][t] + red[2][t] + red[3][t];
    __syncthreads();

    #pragma unroll
    for (int i = 0; i < 16; i++) wA[i] = W3n[(p0 + i) * 64 + o];
    {
        float s = 0.f;
        #pragma unroll
        for (int i = 0; i < 16; i++) s = fmaf(wB[i], sG1[p0 + i], s);
        red[q][o] = s;
    }
    __syncthreads();
    if (t < 64) sG2[t] = red[0][t] + red[1][t] + red[2][t] + red[3][t];
    __syncthreads();

    #pragma unroll
    for (int i = 0; i < 16; i++) wB[i] = WLn[(p0 + i) * 64 + o];
    {
        float s = 0.f;
        #pragma unroll
        for (int i = 0; i < 16; i++) s = fmaf(wA[i], sG2[p0 + i], s);
        red[q][o] = s;
    }
    __syncthreads();
    if (t < 64) sG3[t] = red[0][t] + red[1][t] + red[2][t] + red[3][t];
    __syncthreads();

    {
        float s = 0.f;
        #pragma unroll
        for (int i = 0; i < 16; i++) s = fmaf(wB[i], sG3[p0 + i], s);
        red[q][o] = s;
    }
    __syncthreads();
    if (t < 64) g_part[k][t] = red[0][t] + red[1][t] + red[2][t] + red[3][t];

    if (t < 64) {
        float s = sG3[o] * bleaf[k * 64 + o];
        if ((k & 1) == 0) s = fmaf(sG2[o], b3[(k >> 1) * 64 + o], s);
        if ((k & 3) == 0) s = fmaf(sG1[o], b2[(k >> 2) * 64 + o], s);
        if (k == 0)       s = fmaf(sGr[o], b1[o] + b1[64 + o], s);
        cp[o] = s;
    }
    __syncthreads();
    if (t == 0) {
        float s = (k == 0) ? br[0] : 0.f;
        #pragma unroll 8
        for (int i = 0; i < 64; i++) s += cp[i];
        c_part[k] = s;
    }
    __syncthreads();

    cudaTriggerProgrammaticLaunchCompletion();
}

// ---------------------------------------------------------------------------
// Main kernel (PDL secondary). 32 samples (2 chunks) per warp-iteration.
//   Lane l < 16: sample = base + l (chunk A, sA row l)
//   Lane l >=16: sample = base + l  (chunk B, sA row l)
//   Each lane stages its FULL 16-word A row (K=32 bf16):
//     w0-4 = H0..H4 (x_hi, cols 0-9)   w5-9  = L0..L4 (x_lo, cols 10-19)
//     w10-14 = H0..H4 (cols 20-29)     w15   = ONES   (cols 30-31)
//   B cols: [W_hi(10) | W_hi(10) | W_lo(10) | bt_hi, bt_lo]
//   h = x_hi.W_hi + x_lo.W_hi + x_hi.W_lo + bt  (fp32 accum, ~1e-5 rel)
// ---------------------------------------------------------------------------
__global__ void __launch_bounds__(128, 7)
tree_main_kernel(const float* __restrict__ x, const float* __restrict__ Wt,
                 const float* __restrict__ bt, float* __restrict__ out,
                 int N, int n_pairs) {
    __shared__ uint32_t sB[64][18];       // [out][k-pair], 72B rows
    __shared__ uint32_t sA[4][32][20];    // per warp: 32 rows x 80B
    __shared__ uint4 sFrag[8][32];        // [n-tile][lane]
    __shared__ float sWeff[64];
    __shared__ float sC[1];

    const int t = threadIdx.x;
    const int wid = t >> 5, lane = t & 31;
    const int c = lane & 3, g = lane >> 2;

    // ---- build B tile (independent of compose; overlaps it under PDL) ----
    if (t < 64) {
        const float2* wr = (const float2*)(Wt + t * 10);
        uint32_t H[5], L[5];
        #pragma unroll
        for (int j = 0; j < 5; j++) {
            const float2 v = wr[j];
            H[j] = bfpk(v.x, v.y);
            L[j] = bfpk(v.x - bflo(H[j]), v.y - bfhi(H[j]));
        }
        const float bv = bt[t];
        const uint32_t bh = bfpk(bv, 0.f);
        const uint32_t bp = bfpk(bv, bv - bflo(bh));   // {bt_hi, bt_lo}
        #pragma unroll
        for (int j = 0; j < 5; j++) {
            sB[t][j]      = H[j];   // k 0-9  : W_hi
            sB[t][5 + j]  = H[j];   // k 10-19: W_hi
            sB[t][10 + j] = L[j];   // k 20-29: W_lo
        }
        sB[t][15] = bp;             // k 30,31: bt_hi, bt_lo
        sB[t][16] = 0u; sB[t][17] = 0u;
    }
    __syncthreads();

    // ---- precompute per-lane B fragments into smem (warp 0) ----
    if (wid == 0) {
        #pragma unroll
        for (int nt = 0; nt < 8; nt++) {
            const int row = 8 * nt + g;
            sFrag[nt][lane] = make_uint4(sB[row][c],     sB[row][4 + c],
                                         sB[row][8 + c], sB[row][12 + c]);
        }
    }

    // ---- wait for compose results, then reduce w_eff / c ----
    cudaGridDependencySynchronize();
    if (t < 64) {
        float s = 0.f;
        #pragma unroll
        for (int k = 0; k < 16; k++) s += g_part[k][t];
        sWeff[t] = s;
    }
    if (t == 64) {
        float s = 0.f;
        #pragma unroll
        for (int k = 0; k < 16; k++) s += c_part[k];
        sC[0] = s;
    }
    __syncthreads();
    const float cv = sC[0];

    const int lm_sub = lane >> 3, lm_r = lane & 7;
    const int lm_row = lm_r + 8 * (lm_sub & 1);
    const uint32_t lm_base =
        (uint32_t)__cvta_generic_to_shared(&sA[wid][lm_row][0]) + (lm_sub >> 1) * 16;
    const uint32_t lm_base2 = lm_base + 16 * 80;   // rows 16-31 (chunk B)

    const int wglobal = blockIdx.x * 4 + wid;
    const int wstride = gridDim.x * 4;

    for (int pr = wglobal; pr < n_pairs; pr += wstride) {
        const int base = pr * 32;
        // each lane owns ONE sample: row = base + lane  (N % 32 == 0)
        float xv[10];
        {
            const float2* p = (const float2*)(x + (size_t)(base + lane) * 10);
            #pragma unroll
            for (int i = 0; i < 5; i++) { float2 v = p[i]; xv[2*i] = v.x; xv[2*i+1] = v.y; }
        }

        // envelope for this lane's sample
        float env = fmaf(xv[0], xv[0], -1.f);
        #pragma unroll
        for (int d = 1; d < 10; d++) env *= fmaf(xv[d], xv[d], -1.f);
        env = env * rsqrtf(fmaf(env, env, 1000.f));

        // ---- per-lane full-row A staging (no duplication, no SELs) ----
        uint32_t H[5], L[5];
        #pragma unroll
        for (int j = 0; j < 5; j++) {
            H[j] = bfpk(xv[2 * j], xv[2 * j + 1]);
            L[j] = bfpk(xv[2 * j] - bflo(H[j]), xv[2 * j + 1] - bfhi(H[j]));
        }
        uint32_t* arow = sA[wid][lane];
        *(uint4*)&arow[0]  = make_uint4(H[0], H[1], H[2], H[3]);
        *(uint4*)&arow[4]  = make_uint4(H[4], L[0], L[1], L[2]);
        *(uint4*)&arow[8]  = make_uint4(L[3], L[4], H[0], H[1]);
        *(uint4*)&arow[12] = make_uint4(H[2], H[3], H[4], 0x3f803f80u);
        __syncwarp();

        uint32_t a0[4], a1[4], a2[4], a3[4];
        asm volatile("ldmatrix.sync.aligned.m8n8.x4.shared.b16 {%0,%1,%2,%3}, [%4];"
                     : "=r"(a0[0]), "=r"(a0[1]), "=r"(a0[2]), "=r"(a0[3])
                     : "r"(lm_base));
        asm volatile("ldmatrix.sync.aligned.m8n8.x4.shared.b16 {%0,%1,%2,%3}, [%4];"
                     : "=r"(a1[0]), "=r"(a1[1]), "=r"(a1[2]), "=r"(a1[3])
                     : "r"(lm_base + 32));
        asm volatile("ldmatrix.sync.aligned.m8n8.x4.shared.b16 {%0,%1,%2,%3}, [%4];"
                     : "=r"(a2[0]), "=r"(a2[1]), "=r"(a2[2]), "=r"(a2[3])
                     : "r"(lm_base2));
        asm volatile("ldmatrix.sync.aligned.m8n8.x4.shared.b16 {%0,%1,%2,%3}, [%4];"
                     : "=r"(a3[0]), "=r"(a3[1]), "=r"(a3[2]), "=r"(a3[3])
                     : "r"(lm_base2 + 32));

        float accA0 = 0.f, accB0 = 0.f, accA1 = 0.f, accB1 = 0.f;
        #pragma unroll
        for (int nt = 0; nt < 8; nt++) {
            const uint4 bf = sFrag[nt][lane];
            float d0 = 0.f, d1 = 0.f, d2 = 0.f, d3 = 0.f;
            float e0 = 0.f, e1 = 0.f, e2 = 0.f, e3 = 0.f;
            MMA16816(d0, d1, d2, d3, a0, bf.x, bf.y);
            MMA16816(e0, e1, e2, e3, a2, bf.x, bf.y);
            MMA16816(d0, d1, d2, d3, a1, bf.z, bf.w);
            MMA16816(e0, e1, e2, e3, a3, bf.z, bf.w);

            const float2 wv = *(const float2*)&sWeff[8 * nt + 2 * c];
            float s0, s1, s2, s3, u0, u1, u2, u3;
            asm("sin.approx.f32 %0, %1;" : "=f"(s0) : "f"(d0));
            asm("sin.approx.f32 %0, %1;" : "=f"(s1) : "f"(d1));
            asm("sin.approx.f32 %0, %1;" : "=f"(s2) : "f"(d2));
            asm("sin.approx.f32 %0, %1;" : "=f"(s3) : "f"(d3));
            asm("sin.approx.f32 %0, %1;" : "=f"(u0) : "f"(e0));
            asm("sin.approx.f32 %0, %1;" : "=f"(u1) : "f"(e1));
            asm("sin.approx.f32 %0, %1;" : "=f"(u2) : "f"(e2));
            asm("sin.approx.f32 %0, %1;" : "=f"(u3) : "f"(e3));
            accA0 = fmaf(s0, wv.x, accA0);
            accA0 = fmaf(s1, wv.y, accA0);
            accB0 = fmaf(s2, wv.x, accB0);
            accB0 = fmaf(s3, wv.y, accB0);
            accA1 = fmaf(u0, wv.x, accA1);
            accA1 = fmaf(u1, wv.y, accA1);
            accB1 = fmaf(u2, wv.x, accB1);
            accB1 = fmaf(u3, wv.y, accB1);
        }

        // reduce over the 4 lanes (c=0..3) sharing the same sample rows
        accA0 += __shfl_xor_sync(0xffffffffu, accA0, 1);
        accB0 += __shfl_xor_sync(0xffffffffu, accB0, 1);
        accA1 += __shfl_xor_sync(0xffffffffu, accA1, 1);
        accB1 += __shfl_xor_sync(0xffffffffu, accB1, 1);
        accA0 += __shfl_xor_sync(0xffffffffu, accA0, 2);
        accB0 += __shfl_xor_sync(0xffffffffu, accB0, 2);
        accA1 += __shfl_xor_sync(0xffffffffu, accA1, 2);
        accB1 += __shfl_xor_sync(0xffffffffu, accB1, 2);

        // envelope lives in the lane owning that sample
        const float e0G  = __shfl_sync(0xffffffffu, env, g);        // chunk A row g
        const float e0G8 = __shfl_sync(0xffffffffu, env, g + 8);    // chunk A row g+8
        const float e1G  = __shfl_sync(0xffffffffu, env, g + 16);   // chunk B row g
        const float e1G8 = __shfl_sync(0xffffffffu, env, g + 24);   // chunk B row g+8

        if (c == 0) {
            out[base + g]      = e0G * (accA0 + cv);
            out[base + 16 + g] = e1G * (accA1 + cv);
        }
        if (c == 1) {
            out[base + 8 + g]  = e0G8 * (accB0 + cv);
            out[base + 24 + g] = e1G8 * (accB1 + cv);
        }
    }
}

// ---------------------------------------------------------------------------
extern "C" void kernel_launch(void* const* d_in, const int* in_sizes, int n_in,
                              void* d_out, int out_size) {
    const float* x     = (const float*)d_in[0];
    const float* Wt    = (const float*)d_in[1];
    const float* bt    = (const float*)d_in[2];
    const float* Wleaf = (const float*)d_in[3];
    const float* bleaf = (const float*)d_in[4];
    const float* W3    = (const float*)d_in[5];
    const float* b3    = (const float*)d_in[6];
    const float* W2    = (const float*)d_in[7];
    const float* b2    = (const float*)d_in[8];
    const float* W1    = (const float*)d_in[9];
    const float* b1    = (const float*)d_in[10];
    const float* Wr    = (const float*)d_in[11];
    const float* br    = (const float*)d_in[12];
    float* out = (float*)d_out;

    const int N = in_sizes[0] / 10;
    const int n_pairs = (N + 31) / 32;   // 8192 for N=262144

    compose_kernel<<<16, 256>>>(Wleaf, bleaf, W3, b3, W2, b2, W1, b1, Wr, br);

    // grid: 2 pair-iterations per warp, single wave (1024 <= 148*7)
    int grid = (n_pairs + 7) / 8;
    if (grid < 1) grid = 1;

    cudaLaunchConfig_t cfg = {};
    cfg.gridDim = dim3((unsigned)grid, 1, 1);
    cfg.blockDim = dim3(128, 1, 1);
    cfg.dynamicSmemBytes = 0;
    cudaLaunchAttribute attrs[1];
    attrs[0].id = cudaLaunchAttributeProgrammaticStreamSerialization;
    attrs[0].val.programmaticStreamSerializationAllowed = 1;
    cfg.attrs = attrs;
    cfg.numAttrs = 1;
    cudaLaunchKernelEx(&cfg, tree_main_kernel, x, Wt, bt, out, N, n_pairs);
}

// round 17
// speedup vs baseline: 1.2278x; 1.1041x over previous
#include <cuda_runtime.h>
#include <cuda_bf16.h>
#include <cstdint>

// ===========================================================================
// TrainableTree: out[n] = a(x_n) * ( sin(Wt x_n + bt) . w_eff + c )
// Tree after sin() is linear with OUT=1 -> collapses to (w_eff[64], c).
// compose_kernel: ALL weight traffic issued at t=0 (W1/W2 -> regs,
//   W3/Wleaf -> smem via cp.async) => one DRAM-latency round total. PDL
//   trigger on completion.
// tree_main_kernel (PDL secondary, byte-identical loop to R16 best):
//   2 chunks (32 samples)/warp-iter, per-lane dedup staging,
//   HMMA (bf16 hi/lo split, fp32 accum) -> MUFU sin -> dot -> envelope.
// ===========================================================================

__device__ float g_part[16][64];   // per-leaf partials of w_eff
__device__ float c_part[16];       // per-leaf partials of c

// ---------------- helpers ----------------
__device__ __forceinline__ uint32_t bfpk(float lo, float hi) {
    uint32_t d;
    asm("cvt.rn.bf16x2.f32 %0, %1, %2;" : "=r"(d) : "f"(hi), "f"(lo));
    return d;   // lower 16 = bf16(lo), upper 16 = bf16(hi)
}
__device__ __forceinline__ float bflo(uint32_t p) { return __uint_as_float(p << 16); }
__device__ __forceinline__ float bfhi(uint32_t p) { return __uint_as_float(p & 0xffff0000u); }

#define MMA16816(d0,d1,d2,d3,a,b0,b1) \
    asm volatile( \
        "mma.sync.aligned.m16n8k16.row.col.f32.bf16.bf16.f32 " \
        "{%0,%1,%2,%3}, {%4,%5,%6,%7}, {%8,%9}, {%0,%1,%2,%3};" \
        : "+f"(d0), "+f"(d1), "+f"(d2), "+f"(d3) \
        : "r"((a)[0]), "r"((a)[1]), "r"((a)[2]), "r"((a)[3]), \
          "r"(b0), "r"(b1))

// ---------------------------------------------------------------------------
// Compose: 16 blocks x 256 thr. Block k uses W1[k>>3], W2[k>>2], W3[k>>1],
// Wleaf[k]. W1/W2 -> 32 regs (upfront LDG); W3/Wleaf -> smem via cp.async
// (two commit groups, issued at t=0). All four transfers overlap; each stage
// is then pure smem/FMA with a short wait.
// ---------------------------------------------------------------------------
__global__ void __launch_bounds__(256)
compose_kernel(const float* __restrict__ Wleaf, const float* __restrict__ bleaf,
               const float* __restrict__ W3, const float* __restrict__ b3,
               const float* __restrict__ W2, const float* __restrict__ b2,
               const float* __restrict__ W1, const float* __restrict__ b1,
               const float* __restrict__ Wr, const float* __restrict__ br) {
    __shared__ float sW3[4096];    // 16 KB
    __shared__ float sWL[4096];    // 16 KB
    __shared__ float sGr[64], sG1[64], sG2[64], sG3[64];
    __shared__ float red[4][64];
    __shared__ float cp[64];

    const int t = threadIdx.x;
    const int k = blockIdx.x;
    const int o = t & 63, q = t >> 6;   // q in 0..3
    const int p0 = q * 16;

    // ---- cp.async: W3 slice then Wleaf slice, issued immediately ----
    {
        const float4* srcW3 = (const float4*)(W3 + (k >> 1) * 4096);
        const float4* srcWL = (const float4*)(Wleaf + k * 4096);
        const uint32_t d3 = (uint32_t)__cvta_generic_to_shared(sW3) + t * 16;
        const uint32_t dl = (uint32_t)__cvta_generic_to_shared(sWL) + t * 16;
        #pragma unroll
        for (int i = 0; i < 4; i++)
            asm volatile("cp.async.cg.shared.global [%0], [%1], 16;"
                         :: "r"(d3 + i * 4096), "l"(srcW3 + t + 256 * i));
        asm volatile("cp.async.commit_group;");
        #pragma unroll
        for (int i = 0; i < 4; i++)
            asm volatile("cp.async.cg.shared.global [%0], [%1], 16;"
                         :: "r"(dl + i * 4096), "l"(srcWL + t + 256 * i));
        asm volatile("cp.async.commit_group;");
    }

    // ---- W1/W2 slices into registers (independent; same latency round) ----
    const float* W1n = W1 + (k >> 3) * 4096;
    const float* W2n = W2 + (k >> 2) * 4096;
    float w1r[16], w2r[16];
    #pragma unroll
    for (int i = 0; i < 16; i++) w1r[i] = W1n[(p0 + i) * 64 + o];
    #pragma unroll
    for (int i = 0; i < 16; i++) w2r[i] = W2n[(p0 + i) * 64 + o];

    // biases upfront
    const float blf = bleaf[k * 64 + o];
    const float b3v = ((k & 1) == 0) ? b3[(k >> 1) * 64 + o] : 0.f;
    const float b2v = ((k & 3) == 0) ? b2[(k >> 2) * 64 + o] : 0.f;
    const float b1v = (k == 0) ? (b1[o] + b1[64 + o]) : 0.f;

    if (t < 64) sGr[t] = Wr[t];
    __syncthreads();

    // stage 1: g1 = gr . W1
    {
        float s = 0.f;
        #pragma unroll
        for (int i = 0; i < 16; i++) s = fmaf(w1r[i], sGr[p0 + i], s);
        red[q][o] = s;
    }
    __syncthreads();
    if (t < 64) sG1[t] = red[0][t] + red[1][t] + red[2][t] + red[3][t];
    __syncthreads();

    // stage 2: g2 = g1 . W2
    {
        float s = 0.f;
        #pragma unroll
        for (int i = 0; i < 16; i++) s = fmaf(w2r[i], sG1[p0 + i], s);
        red[q][o] = s;
    }
    __syncthreads();
    if (t < 64) sG2[t] = red[0][t] + red[1][t] + red[2][t] + red[3][t];
    __syncthreads();

    // stage 3: g3 = g2 . W3 (smem, cp.async group 0)
    asm volatile("cp.async.wait_group 1;");
    __syncthreads();
    {
        float s = 0.f;
        #pragma unroll
        for (int i = 0; i < 16; i++) s = fmaf(sW3[(p0 + i) * 64 + o], sG2[p0 + i], s);
        red[q][o] = s;
    }
    __syncthreads();
    if (t < 64) sG3[t] = red[0][t] + red[1][t] + red[2][t] + red[3][t];
    __syncthreads();

    // stage 4: w_eff partial = g3 . Wleaf (smem, cp.async group 1)
    asm volatile("cp.async.wait_group 0;");
    __syncthreads();
    {
        float s = 0.f;
        #pragma unroll
        for (int i = 0; i < 16; i++) s = fmaf(sWL[(p0 + i) * 64 + o], sG3[p0 + i], s);
        red[q][o] = s;
    }
    __syncthreads();
    if (t < 64) g_part[k][t] = red[0][t] + red[1][t] + red[2][t] + red[3][t];

    // bias partials (each term counted once across blocks)
    if (t < 64) {
        float s = sG3[o] * blf;
        s = fmaf(sG2[o], b3v, s);
        s = fmaf(sG1[o], b2v, s);
        s = fmaf(sGr[o], b1v, s);
        cp[o] = s;
    }
    __syncthreads();
    if (t == 0) {
        float s = (k == 0) ? br[0] : 0.f;
        #pragma unroll 8
        for (int i = 0; i < 64; i++) s += cp[i];
        c_part[k] = s;
    }
    __syncthreads();

    cudaTriggerProgrammaticLaunchCompletion();
}

// ---------------------------------------------------------------------------
// Main kernel (PDL secondary). 32 samples (2 chunks) per warp-iteration.
//   Lane l owns sample base+l: loads x, splits hi/lo, envelopes, writes its
//   full 16-word A row (K=32 bf16). ldmatrix x4 twice per chunk.
//   B cols: [W_hi(10) | W_hi(10) | W_lo(10) | bt_hi, bt_lo]
//   h = x_hi.W_hi + x_lo.W_hi + x_hi.W_lo + bt  (fp32 accum, ~1e-5 rel)
// ---------------------------------------------------------------------------
__global__ void __launch_bounds__(128, 7)
tree_main_kernel(const float* __restrict__ x, const float* __restrict__ Wt,
                 const float* __restrict__ bt, float* __restrict__ out,
                 int N, int n_pairs) {
    __shared__ uint32_t sB[64][18];       // [out][k-pair], 72B rows
    __shared__ uint32_t sA[4][32][20];    // per warp: 32 rows x 80B
    __shared__ uint4 sFrag[8][32];        // [n-tile][lane]
    __shared__ float sWeff[64];
    __shared__ float sC[1];

    const int t = threadIdx.x;
    const int wid = t >> 5, lane = t & 31;
    const int c = lane & 3, g = lane >> 2;

    // ---- build B tile (independent of compose; overlaps it under PDL) ----
    if (t < 64) {
        const float2* wr = (const float2*)(Wt + t * 10);
        uint32_t H[5], L[5];
        #pragma unroll
        for (int j = 0; j < 5; j++) {
            const float2 v = wr[j];
            H[j] = bfpk(v.x, v.y);
            L[j] = bfpk(v.x - bflo(H[j]), v.y - bfhi(H[j]));
        }
        const float bv = bt[t];
        const uint32_t bh = bfpk(bv, 0.f);
        const uint32_t bp = bfpk(bv, bv - bflo(bh));   // {bt_hi, bt_lo}
        #pragma unroll
        for (int j = 0; j < 5; j++) {
            sB[t][j]      = H[j];   // k 0-9  : W_hi
            sB[t][5 + j]  = H[j];   // k 10-19: W_hi
            sB[t][10 + j] = L[j];   // k 20-29: W_lo
        }
        sB[t][15] = bp;             // k 30,31: bt_hi, bt_lo
        sB[t][16] = 0u; sB[t][17] = 0u;
    }
    __syncthreads();

    // ---- precompute per-lane B fragments into smem (warp 0) ----
    if (wid == 0) {
        #pragma unroll
        for (int nt = 0; nt < 8; nt++) {
            const int row = 8 * nt + g;
            sFrag[nt][lane] = make_uint4(sB[row][c],     sB[row][4 + c],
                                         sB[row][8 + c], sB[row][12 + c]);
        }
    }

    // ---- wait for compose results, then reduce w_eff / c ----
    cudaGridDependencySynchronize();
    if (t < 64) {
        float s = 0.f;
        #pragma unroll
        for (int k = 0; k < 16; k++) s += g_part[k][t];
        sWeff[t] = s;
    }
    if (t == 64) {
        float s = 0.f;
        #pragma unroll
        for (int k = 0; k < 16; k++) s += c_part[k];
        sC[0] = s;
    }
    __syncthreads();
    const float cv = sC[0];

    const int lm_sub = lane >> 3, lm_r = lane & 7;
    const int lm_row = lm_r + 8 * (lm_sub & 1);
    const uint32_t lm_base =
        (uint32_t)__cvta_generic_to_shared(&sA[wid][lm_row][0]) + (lm_sub >> 1) * 16;
    const uint32_t lm_base2 = lm_base + 16 * 80;   // rows 16-31 (chunk B)

    const int wglobal = blockIdx.x * 4 + wid;
    const int wstride = gridDim.x * 4;

    for (int pr = wglobal; pr < n_pairs; pr += wstride) {
        const int base = pr * 32;
        // each lane owns ONE sample: row = base + lane  (N % 32 == 0)
        float xv[10];
        {
            const float2* p = (const float2*)(x + (size_t)(base + lane) * 10);
            #pragma unroll
            for (int i = 0; i < 5; i++) { float2 v = p[i]; xv[2*i] = v.x; xv[2*i+1] = v.y; }
        }

        // envelope for this lane's sample
        float env = fmaf(xv[0], xv[0], -1.f);
        #pragma unroll
        for (int d = 1; d < 10; d++) env *= fmaf(xv[d], xv[d], -1.f);
        env = env * rsqrtf(fmaf(env, env, 1000.f));

        // ---- per-lane full-row A staging (no duplication, no SELs) ----
        uint32_t H[5], L[5];
        #pragma unroll
        for (int j = 0; j < 5; j++) {
            H[j] = bfpk(xv[2 * j], xv[2 * j + 1]);
            L[j] = bfpk(xv[2 * j] - bflo(H[j]), xv[2 * j + 1] - bfhi(H[j]));
        }
        uint32_t* arow = sA[wid][lane];
        *(uint4*)&arow[0]  = make_uint4(H[0], H[1], H[2], H[3]);
        *(uint4*)&arow[4]  = make_uint4(H[4], L[0], L[1], L[2]);
        *(uint4*)&arow[8]  = make_uint4(L[3], L[4], H[0], H[1]);
        *(uint4*)&arow[12] = make_uint4(H[2], H[3], H[4], 0x3f803f80u);
        __syncwarp();

        uint32_t a0[4], a1[4], a2[4], a3[4];
        asm volatile("ldmatrix.sync.aligned.m8n8.x4.shared.b16 {%0,%1,%2,%3}, [%4];"
                     : "=r"(a0[0]), "=r"(a0[1]), "=r"(a0[2]), "=r"(a0[3])
                     : "r"(lm_base));
        asm volatile("ldmatrix.sync.aligned.m8n8.x4.shared.b16 {%0,%1,%2,%3}, [%4];"
                     : "=r"(a1[0]), "=r"(a1[1]), "=r"(a1[2]), "=r"(a1[3])
                     : "r"(lm_base + 32));
        asm volatile("ldmatrix.sync.aligned.m8n8.x4.shared.b16 {%0,%1,%2,%3}, [%4];"
                     : "=r"(a2[0]), "=r"(a2[1]), "=r"(a2[2]), "=r"(a2[3])
                     : "r"(lm_base2));
        asm volatile("ldmatrix.sync.aligned.m8n8.x4.shared.b16 {%0,%1,%2,%3}, [%4];"
                     : "=r"(a3[0]), "=r"(a3[1]), "=r"(a3[2]), "=r"(a3[3])
                     : "r"(lm_base2 + 32));

        float accA0 = 0.f, accB0 = 0.f, accA1 = 0.f, accB1 = 0.f;
        #pragma unroll
        for (int nt = 0; nt < 8; nt++) {
            const uint4 bf = sFrag[nt][lane];
            float d0 = 0.f, d1 = 0.f, d2 = 0.f, d3 = 0.f;
            float e0 = 0.f, e1 = 0.f, e2 = 0.f, e3 = 0.f;
            MMA16816(d0, d1, d2, d3, a0, bf.x, bf.y);
            MMA16816(e0, e1, e2, e3, a2, bf.x, bf.y);
            MMA16816(d0, d1, d2, d3, a1, bf.z, bf.w);
            MMA16816(e0, e1, e2, e3, a3, bf.z, bf.w);

            const float2 wv = *(const float2*)&sWeff[8 * nt + 2 * c];
            float s0, s1, s2, s3, u0, u1, u2, u3;
            asm("sin.approx.f32 %0, %1;" : "=f"(s0) : "f"(d0));
            asm("sin.approx.f32 %0, %1;" : "=f"(s1) : "f"(d1));
            asm("sin.approx.f32 %0, %1;" : "=f"(s2) : "f"(d2));
            asm("sin.approx.f32 %0, %1;" : "=f"(s3) : "f"(d3));
            asm("sin.approx.f32 %0, %1;" : "=f"(u0) : "f"(e0));
            asm("sin.approx.f32 %0, %1;" : "=f"(u1) : "f"(e1));
            asm("sin.approx.f32 %0, %1;" : "=f"(u2) : "f"(e2));
            asm("sin.approx.f32 %0, %1;" : "=f"(u3) : "f"(e3));
            accA0 = fmaf(s0, wv.x, accA0);
            accA0 = fmaf(s1, wv.y, accA0);
            accB0 = fmaf(s2, wv.x, accB0);
            accB0 = fmaf(s3, wv.y, accB0);
            accA1 = fmaf(u0, wv.x, accA1);
            accA1 = fmaf(u1, wv.y, accA1);
            accB1 = fmaf(u2, wv.x, accB1);
            accB1 = fmaf(u3, wv.y, accB1);
        }

        // reduce over the 4 lanes (c=0..3) sharing the same sample rows
        accA0 += __shfl_xor_sync(0xffffffffu, accA0, 1);
        accB0 += __shfl_xor_sync(0xffffffffu, accB0, 1);
        accA1 += __shfl_xor_sync(0xffffffffu, accA1, 1);
        accB1 += __shfl_xor_sync(0xffffffffu, accB1, 1);
        accA0 += __shfl_xor_sync(0xffffffffu, accA0, 2);
        accB0 += __shfl_xor_sync(0xffffffffu, accB0, 2);
        accA1 += __shfl_xor_sync(0xffffffffu, accA1, 2);
        accB1 += __shfl_xor_sync(0xffffffffu, accB1, 2);

        // envelope lives in the lane owning that sample
        const float e0G  = __shfl_sync(0xffffffffu, env, g);        // chunk A row g
        const float e0G8 = __shfl_sync(0xffffffffu, env, g + 8);    // chunk A row g+8
        const float e1G  = __shfl_sync(0xffffffffu, env, g + 16);   // chunk B row g
        const float e1G8 = __shfl_sync(0xffffffffu, env, g + 24);   // chunk B row g+8

        if (c == 0) {
            out[base + g]      = e0G * (accA0 + cv);
            out[base + 16 + g] = e1G * (accA1 + cv);
        }
        if (c == 1) {
            out[base + 8 + g]  = e0G8 * (accB0 + cv);
            out[base + 24 + g] = e1G8 * (accB1 + cv);
        }
    }
}

// ---------------------------------------------------------------------------
extern "C" void kernel_launch(void* const* d_in, const int* in_sizes, int n_in,
                              void* d_out, int out_size) {
    const float* x     = (const float*)d_in[0];
    const float* Wt    = (const float*)d_in[1];
    const float* bt    = (const float*)d_in[2];
    const float* Wleaf = (const float*)d_in[3];
    const float* bleaf = (const float*)d_in[4];
    const float* W3    = (const float*)d_in[5];
    const float* b3    = (const float*)d_in[6];
    const float* W2    = (const float*)d_in[7];
    const float* b2    = (const float*)d_in[8];
    const float* W1    = (const float*)d_in[9];
    const float* b1    = (const float*)d_in[10];
    const float* Wr    = (const float*)d_in[11];
    const float* br    = (const float*)d_in[12];
    float* out = (float*)d_out;

    const int N = in_sizes[0] / 10;
    const int n_pairs = (N + 31) / 32;   // 8192 for N=262144

    compose_kernel<<<16, 256>>>(Wleaf, bleaf, W3, b3, W2, b2, W1, b1, Wr, br);

    // grid: 2 pair-iterations per warp, single wave (1024 <= 148*7)
    int grid = (n_pairs + 7) / 8;
    if (grid < 1) grid = 1;

    cudaLaunchConfig_t cfg = {};
    cfg.gridDim = dim3((unsigned)grid, 1, 1);
    cfg.blockDim = dim3(128, 1, 1);
    cfg.dynamicSmemBytes = 0;
    cudaLaunchAttribute attrs[1];
    attrs[0].id = cudaLaunchAttributeProgrammaticStreamSerialization;
    attrs[0].val.programmaticStreamSerializationAllowed = 1;
    cfg.attrs = attrs;
    cfg.numAttrs = 1;
    cudaLaunchKernelEx(&cfg, tree_main_kernel, x, Wt, bt, out, N, n_pairs);
}